// round 7
// baseline (speedup 1.0000x reference)
#include <cuda_runtime.h>
#include <cuda_bf16.h>
#include <cstdint>

// Deformable Conv3d via portable HMMA (mma.sync.m16n8k16.bf16, hi/lo split).
// R7: - B operands pre-arranged in GLOBAL in mma fragment order (no B smem,
//       no staging, loaded with broadcast LDG.128, L1-hot across 8 warps)
//     - per-warp-pair named barriers (bar.sync mt,64) instead of block sync
//     - AND-wrap gather addressing (wgt=0 already kills invalid taps)
//     - offsets pre-transposed to [b][p][k][4] -> 1 broadcast LDG.128/pt/tap

namespace {
constexpr int B_ = 2, CIN_ = 64, COUT_ = 64, D_ = 8, H_ = 32, W_ = 32, K_ = 27;
constexpr int P_ = D_ * H_ * W_;              // 8192
constexpr int MTILE = 128;
constexpr int THREADS = 512;
constexpr int NBLK = (B_ * P_) / MTILE;       // 128

// dynamic smem: A only, [buf][hi 16K | lo 16K]
constexpr int SM_TOTAL = 2 * 32768;           // 65536
constexpr unsigned FULL = 0xffffffffu;
}

__device__ __align__(256) float g_xT[B_ * P_ * CIN_];           // channels-last x
__device__ __align__(256) uint32_t g_wF[K_ * 2 * 8 * 32 * 8];   // B fragments
__device__ __align__(256) float4 g_offT[B_ * P_ * K_];          // offsets [b][p][k]

// ---------------- helpers ----------------
__device__ __forceinline__ uint32_t smem_u32(const void* p) {
    uint32_t a;
    asm("{ .reg .u64 t; cvta.to.shared.u64 t, %1; cvt.u32.u64 %0, t; }"
        : "=r"(a) : "l"(p));
    return a;
}
__device__ __forceinline__ uint32_t bf16x2(float hi_elem, float lo_elem) {
    uint32_t r;
    asm("cvt.rn.bf16x2.f32 %0, %1, %2;" : "=r"(r) : "f"(hi_elem), "f"(lo_elem));
    return r;
}
__device__ __forceinline__ void ldm_x4(uint32_t* r, uint32_t addr) {
    asm volatile("ldmatrix.sync.aligned.m8n8.x4.shared.b16 {%0,%1,%2,%3}, [%4];"
                 : "=r"(r[0]), "=r"(r[1]), "=r"(r[2]), "=r"(r[3]) : "r"(addr));
}
__device__ __forceinline__ void mma_bf16(float* c, const uint32_t* a,
                                         const uint32_t* b) {
    asm volatile(
        "mma.sync.aligned.m16n8k16.row.col.f32.bf16.bf16.f32 "
        "{%0,%1,%2,%3}, {%4,%5,%6,%7}, {%8,%9}, {%0,%1,%2,%3};"
        : "+f"(c[0]), "+f"(c[1]), "+f"(c[2]), "+f"(c[3])
        : "r"(a[0]), "r"(a[1]), "r"(a[2]), "r"(a[3]), "r"(b[0]), "r"(b[1]));
}
__device__ __forceinline__ void bar_pair(int id) {
    asm volatile("bar.sync %0, 64;" :: "r"(id) : "memory");
}

// ---------------- prep ----------------
__global__ void prep_kernel(const float* __restrict__ x,
                            const float* __restrict__ w,
                            const float* __restrict__ offset) {
    const int stride = gridDim.x * blockDim.x;
    const int tid = blockIdx.x * blockDim.x + threadIdx.x;

    // x [b][c][p] -> xT [b][p][c]
    for (int i = tid; i < B_ * CIN_ * P_; i += stride) {
        int s = i % P_;
        int c = (i / P_) % CIN_;
        int b = i / (P_ * CIN_);
        g_xT[(b * P_ + s) * CIN_ + c] = x[i];
    }

    // weight [o][c][k] -> mma B fragments: [kt][hl][jg][lane][ks*2+reg]
    for (int i = tid; i < K_ * 2 * 8 * 32 * 8; i += stride) {
        int u    = i & 7;
        int ln   = (i >> 3) & 31;
        int jg   = (i >> 8) & 7;
        int hl   = (i >> 11) & 1;
        int kt   = i >> 12;
        int ks   = u >> 1, reg = u & 1;
        int n = jg * 8 + (ln >> 2);
        int c = ks * 16 + (ln & 3) * 2 + reg * 8;
        float v0 = w[(n * CIN_ + c) * K_ + kt];
        float v1 = w[(n * CIN_ + c + 1) * K_ + kt];
        __nv_bfloat16 h0 = __float2bfloat16(v0);
        __nv_bfloat16 h1 = __float2bfloat16(v1);
        uint32_t valu;
        if (hl == 0) {
            valu = ((uint32_t)__bfloat16_as_ushort(h1) << 16) |
                   (uint32_t)__bfloat16_as_ushort(h0);
        } else {
            __nv_bfloat16 l0 = __float2bfloat16(v0 - __bfloat162float(h0));
            __nv_bfloat16 l1 = __float2bfloat16(v1 - __bfloat162float(h1));
            valu = ((uint32_t)__bfloat16_as_ushort(l1) << 16) |
                   (uint32_t)__bfloat16_as_ushort(l0);
        }
        g_wF[i] = valu;
    }

    // offset [b][3K][p] -> [b][p][kt]{d,h,w,0} (p fastest: coalesced reads)
    for (int i = tid; i < B_ * P_ * K_; i += stride) {
        int p  = i % P_;
        int kt = (i / P_) % K_;
        int b  = i / (P_ * K_);
        const float* ob = offset + (size_t)b * 3 * K_ * P_;
        float4 v;
        v.x = ob[(3 * kt + 0) * P_ + p];
        v.y = ob[(3 * kt + 1) * P_ + p];
        v.z = ob[(3 * kt + 2) * P_ + p];
        v.w = 0.f;
        g_offT[(size_t)(b * P_ + p) * K_ + kt] = v;
    }
}

// ---------------- main ----------------
__global__ __launch_bounds__(THREADS, 1)
void deform_hmma_kernel(const float* __restrict__ bias,
                        float* __restrict__ out) {
    extern __shared__ __align__(1024) char smem[];
    const uint32_t sb = smem_u32(smem);

    const int tid  = threadIdx.x;
    const int lane = tid & 31;
    const int warp = tid >> 5;               // 16 warps
    const int blk  = blockIdx.x;
    const int b    = blk >> 6;
    const int p0   = (blk & 63) * MTILE;

    const char* xb = reinterpret_cast<const char*>(g_xT + (size_t)b * P_ * CIN_);
    const float4* offT = g_offT + (size_t)b * P_ * K_;

    // sampling role
    const int half = lane >> 4;              // d-plane half
    const int c4   = lane & 15;              // float4 channel chunk
    const int pl_base = warp * 8;
    uint32_t wAoff[8];
#pragma unroll
    for (int i = 0; i < 8; i++) {
        int pl = pl_base + i;
        wAoff[i] = (uint32_t)(pl * 128 + ((c4 * 8) ^ ((pl & 7) << 4)));
    }

    // mma role: warp (mt, nt) owns D[mt*16..+15][nt*32..+31]
    const int mt = warp >> 1, nt = warp & 1;
    const int rowA = mt * 16 + (lane & 15);
    const uint32_t aBaseOff = (uint32_t)(rowA * 128);
    const uint32_t aXor = (uint32_t)((rowA & 7) << 4);
    const uint32_t aKh  = (uint32_t)((lane >> 4) << 4);

    float acc[4][4];
#pragma unroll
    for (int j = 0; j < 4; j++)
#pragma unroll
        for (int q = 0; q < 4; q++) acc[j][q] = 0.f;

    const uint4* gF = reinterpret_cast<const uint4*>(g_wF);

#pragma unroll 1
    for (int kt = 0; kt < K_; kt++) {
        const int buf = kt & 1;
        char* AhP = smem + buf * 32768;
        char* AlP = AhP + 16384;
        const uint32_t AhB = sb + buf * 32768;
        const uint32_t AlB = AhB + 16384;

        // ---- sampling: 8 points per warp ----
        const int kd = kt / 9, kh3 = (kt / 3) % 3, kw3 = kt % 3;

#pragma unroll
        for (int i = 0; i < 8; i++) {
            const int p  = p0 + pl_base + i;
            const int od = p >> 10, oh = (p >> 5) & 31, ow = p & 31;

            float4 of = __ldg(&offT[(size_t)p * K_ + kt]);   // broadcast
            float zd = (float)(od - 1 + kd) + of.x;
            float zh = (float)(oh - 1 + kh3) + of.y;
            float zw = (float)(ow - 1 + kw3) + of.z;

            float fd = floorf(zd); int d0 = (int)fd; float rd = zd - fd;
            float fh = floorf(zh); int h0 = (int)fh; float rh = zh - fh;
            float fw = floorf(zw); int w0 = (int)fw; float rw = zw - fw;

            // this half's d-plane weight (0 if out of range)
            float wd = half ? (((unsigned)(d0 + 1) < (unsigned)D_) ? rd : 0.f)
                            : (((unsigned)d0 < (unsigned)D_) ? 1.f - rd : 0.f);
            float wh0 = ((unsigned)h0       < (unsigned)H_) ? 1.f - rh : 0.f;
            float wh1 = ((unsigned)(h0 + 1) < (unsigned)H_) ? rh       : 0.f;
            float ww0 = ((unsigned)w0       < (unsigned)W_) ? 1.f - rw : 0.f;
            float ww1 = ((unsigned)(w0 + 1) < (unsigned)W_) ? rw       : 0.f;

            // AND-wrap addresses (wgt=0 makes wrapped values harmless)
            const uint32_t dpl = ((uint32_t)(d0 + half) & 7u) << 18;
            const uint32_t hA  = ((uint32_t)h0 & 31u) << 13;
            const uint32_t hB  = ((uint32_t)(h0 + 1) & 31u) << 13;
            const uint32_t wA  = ((uint32_t)w0 & 31u) << 8;
            const uint32_t wB  = ((uint32_t)(w0 + 1) & 31u) << 8;
            const char* base2 = xb + (dpl + (uint32_t)(c4 << 4));

            const float g0 = wd * (wh0 * ww0), g1 = wd * (wh0 * ww1);
            const float g2 = wd * (wh1 * ww0), g3 = wd * (wh1 * ww1);

            float4 v0 = __ldg(reinterpret_cast<const float4*>(base2 + (hA + wA)));
            float4 v1 = __ldg(reinterpret_cast<const float4*>(base2 + (hA + wB)));
            float4 v2 = __ldg(reinterpret_cast<const float4*>(base2 + (hB + wA)));
            float4 v3 = __ldg(reinterpret_cast<const float4*>(base2 + (hB + wB)));

            float ax = g0 * v0.x + g1 * v1.x + g2 * v2.x + g3 * v3.x;
            float ay = g0 * v0.y + g1 * v1.y + g2 * v2.y + g3 * v3.y;
            float az = g0 * v0.z + g1 * v1.z + g2 * v2.z + g3 * v3.z;
            float aw = g0 * v0.w + g1 * v1.w + g2 * v2.w + g3 * v3.w;

            ax += __shfl_down_sync(FULL, ax, 16);
            ay += __shfl_down_sync(FULL, ay, 16);
            az += __shfl_down_sync(FULL, az, 16);
            aw += __shfl_down_sync(FULL, aw, 16);

            if (half == 0) {
                uint32_t h01 = bf16x2(ay, ax);      // hi=ch+1, lo=ch+0
                uint32_t h23 = bf16x2(aw, az);
                float hx = __uint_as_float(h01 << 16);
                float hy = __uint_as_float(h01 & 0xffff0000u);
                float hz = __uint_as_float(h23 << 16);
                float hww = __uint_as_float(h23 & 0xffff0000u);
                uint32_t l01 = bf16x2(ay - hy, ax - hx);
                uint32_t l23 = bf16x2(aw - hww, az - hz);
                *reinterpret_cast<uint2*>(AhP + wAoff[i]) = make_uint2(h01, h23);
                *reinterpret_cast<uint2*>(AlP + wAoff[i]) = make_uint2(l01, l23);
            }
        }

        bar_pair(mt);   // only the producing/consuming warp pair syncs

        // ---- A fragments: all 4 K-steps, hi+lo ----
        uint32_t ah[4][4], al[4][4];
#pragma unroll
        for (int ks = 0; ks < 4; ks++) {
            const uint32_t aoff = aBaseOff + (((uint32_t)(ks * 32) + aKh) ^ aXor);
            ldm_x4(ah[ks], AhB + aoff);
            ldm_x4(al[ks], AlB + aoff);
        }

        // ---- B fragments from global (fragment-ordered, L1-hot) + MMA ----
#pragma unroll
        for (int j = 0; j < 4; j++) {
            const size_t hiIdx =
                ((size_t)kt * 16 + (nt * 4 + j)) * 64 + lane * 2;
            uint4 q0 = __ldg(gF + hiIdx);
            uint4 q1 = __ldg(gF + hiIdx + 1);
            uint4 r0 = __ldg(gF + hiIdx + 512);   // lo plane (+8*32*8 u32)
            uint4 r1 = __ldg(gF + hiIdx + 513);
            uint32_t bh[8] = {q0.x, q0.y, q0.z, q0.w, q1.x, q1.y, q1.z, q1.w};
            uint32_t bl[8] = {r0.x, r0.y, r0.z, r0.w, r1.x, r1.y, r1.z, r1.w};
#pragma unroll
            for (int ks = 0; ks < 4; ks++) {
                mma_bf16(acc[j], ah[ks], &bh[ks * 2]);
                mma_bf16(acc[j], al[ks], &bh[ks * 2]);
                mma_bf16(acc[j], ah[ks], &bl[ks * 2]);
            }
        }
        // buf reuse at kt+2 is ordered by bar_pair(kt+1)
    }

    // ---- epilogue: D fragment scatter + bias ----
    const int m = lane >> 2;
    const int p = p0 + mt * 16 + m;
#pragma unroll
    for (int j = 0; j < 4; j++) {
        const int n = nt * 32 + j * 8 + 2 * (lane & 3);
        const float bv0 = __ldg(&bias[n]);
        const float bv1 = __ldg(&bias[n + 1]);
        float* o0 = out + ((size_t)(b * COUT_ + n)) * P_ + p;
        o0[0]      = acc[j][0] + bv0;
        o0[P_]     = acc[j][1] + bv1;
        o0[8]      = acc[j][2] + bv0;
        o0[P_ + 8] = acc[j][3] + bv1;
    }
}

extern "C" void kernel_launch(void* const* d_in, const int* in_sizes, int n_in,
                              void* d_out, int out_size) {
    const float* x      = (const float*)d_in[0];
    const float* offset = (const float*)d_in[1];
    const float* weight = (const float*)d_in[2];
    const float* bias   = (const float*)d_in[3];
    float* out = (float*)d_out;

    cudaFuncSetAttribute(deform_hmma_kernel,
                         cudaFuncAttributeMaxDynamicSharedMemorySize, SM_TOTAL);
    prep_kernel<<<1024, 256>>>(x, weight, offset);
    deform_hmma_kernel<<<NBLK, THREADS, SM_TOTAL>>>(bias, out);
}

// round 8
// speedup vs baseline: 1.1582x; 1.1582x over previous
#include <cuda_runtime.h>
#include <cuda_bf16.h>
#include <cstdint>

// Deformable Conv3d via portable HMMA (mma.sync.m16n8k16.bf16, hi/lo split).
// R8: - B weight tiles staged into SMEM in 3 phases (10/10/7 taps, 160KB),
//       consumed via ldmatrix.x4 (kills the 8x per-warp B LDG duplication)
//     - AND-wrap LINEAR-index gather addressing (wgt=0 kills invalid taps)
//     - packed f32x2 corner accumulation
//     - offsets read directly (no transpose prep), x channels-last, A double
//       buffer + per-warp-pair named barriers (ids 1..8)

namespace {
constexpr int B_ = 2, CIN_ = 64, COUT_ = 64, D_ = 8, H_ = 32, W_ = 32, K_ = 27;
constexpr int P_ = D_ * H_ * W_;              // 8192
constexpr int MTILE = 128;
constexpr int THREADS = 512;
constexpr int NBLK = (B_ * P_) / MTILE;       // 128
constexpr int PH   = 10;                      // taps per phase (10,10,7)

// dynamic smem: A [buf][hi 16K | lo 16K] = 64KB, then B phase area 160KB
constexpr int SM_B     = 2 * 32768;           // 65536
constexpr int SM_TOTAL = SM_B + PH * 16384;   // 229376 (224KB)
constexpr unsigned FULL = 0xffffffffu;
}

__device__ __align__(256) float g_xT[B_ * P_ * CIN_];            // channels-last x
// B images, ldmatrix layout: [kt][j(8)][ks(4)][hl(2)][kh(2)][row(8)][16B]
__device__ __align__(256) unsigned char g_wB[K_ * 16384];

// ---------------- helpers ----------------
__device__ __forceinline__ uint32_t smem_u32(const void* p) {
    uint32_t a;
    asm("{ .reg .u64 t; cvta.to.shared.u64 t, %1; cvt.u32.u64 %0, t; }"
        : "=r"(a) : "l"(p));
    return a;
}
__device__ __forceinline__ uint32_t bf16x2(float hi_elem, float lo_elem) {
    uint32_t r;
    asm("cvt.rn.bf16x2.f32 %0, %1, %2;" : "=r"(r) : "f"(hi_elem), "f"(lo_elem));
    return r;
}
__device__ __forceinline__ void ldm_x4(uint32_t* r, uint32_t addr) {
    asm volatile("ldmatrix.sync.aligned.m8n8.x4.shared.b16 {%0,%1,%2,%3}, [%4];"
                 : "=r"(r[0]), "=r"(r[1]), "=r"(r[2]), "=r"(r[3]) : "r"(addr));
}
__device__ __forceinline__ void mma_bf16(float* c, const uint32_t* a,
                                         const uint32_t* b) {
    asm volatile(
        "mma.sync.aligned.m16n8k16.row.col.f32.bf16.bf16.f32 "
        "{%0,%1,%2,%3}, {%4,%5,%6,%7}, {%8,%9}, {%0,%1,%2,%3};"
        : "+f"(c[0]), "+f"(c[1]), "+f"(c[2]), "+f"(c[3])
        : "r"(a[0]), "r"(a[1]), "r"(a[2]), "r"(a[3]), "r"(b[0]), "r"(b[1]));
}
__device__ __forceinline__ void bar_pair(int id) {
    asm volatile("bar.sync %0, 64;" :: "r"(id) : "memory");
}
__device__ __forceinline__ unsigned long long pk2(float x, float y) {
    unsigned long long r;
    asm("mov.b64 %0, {%1, %2};" : "=l"(r) : "f"(x), "f"(y));
    return r;
}
__device__ __forceinline__ void ffma2(unsigned long long& d,
                                      unsigned long long a, unsigned long long b) {
    asm("fma.rn.f32x2 %0, %1, %2, %0;" : "+l"(d) : "l"(a), "l"(b));
}
__device__ __forceinline__ float2 upk(unsigned long long v) {
    float2 f;
    asm("mov.b64 {%0, %1}, %2;" : "=f"(f.x), "=f"(f.y) : "l"(v));
    return f;
}

// ---------------- prep ----------------
__global__ void prep_kernel(const float* __restrict__ x,
                            const float* __restrict__ w) {
    const int stride = gridDim.x * blockDim.x;
    const int tid = blockIdx.x * blockDim.x + threadIdx.x;

    // x [b][c][p] -> xT [b][p][c]
    for (int i = tid; i < B_ * CIN_ * P_; i += stride) {
        int s = i % P_;
        int c = (i / P_) % CIN_;
        int b = i / (P_ * CIN_);
        g_xT[(b * P_ + s) * CIN_ + c] = x[i];
    }

    // weight [o][c][k] -> ldmatrix B images
    // element (kt, n, c): j=n>>3, r=n&7, ks=c>>4, kh=(c>>3)&1, col=c&7
    for (int i = tid; i < K_ * COUT_ * CIN_; i += stride) {
        int c  = i % CIN_;
        int n  = (i / CIN_) % COUT_;
        int kt = i / (CIN_ * COUT_);
        float v = w[(n * CIN_ + c) * K_ + kt];
        __nv_bfloat16 hi = __float2bfloat16(v);
        __nv_bfloat16 lo = __float2bfloat16(v - __bfloat162float(hi));
        int j = n >> 3, r = n & 7, ks = c >> 4, kh = (c >> 3) & 1, col = c & 7;
        size_t base = (size_t)kt * 16384 + (size_t)j * 2048 + (size_t)ks * 512;
        size_t off  = (size_t)kh * 128 + (size_t)r * 16 + (size_t)col * 2;
        *reinterpret_cast<__nv_bfloat16*>(g_wB + base + off)       = hi;  // hl=0
        *reinterpret_cast<__nv_bfloat16*>(g_wB + base + 256 + off) = lo;  // hl=1
    }
}

// ---------------- main ----------------
__global__ __launch_bounds__(THREADS, 1)
void deform_hmma_kernel(const float* __restrict__ offset,
                        const float* __restrict__ bias,
                        float* __restrict__ out) {
    extern __shared__ __align__(1024) char smem[];
    const uint32_t sb = smem_u32(smem);

    const int tid  = threadIdx.x;
    const int lane = tid & 31;
    const int warp = tid >> 5;               // 16 warps
    const int blk  = blockIdx.x;
    const int b    = blk >> 6;
    const int p0   = (blk & 63) * MTILE;

    const float* offB = offset + (size_t)b * 3 * K_ * P_;
    const char*  xb   = reinterpret_cast<const char*>(g_xT + (size_t)b * P_ * CIN_);

    // sampling role
    const int half = lane >> 4;              // d-plane half
    const int c4   = lane & 15;              // float4 channel chunk
    const int pl_base = warp * 8;
    uint32_t wAoff[8];
#pragma unroll
    for (int i = 0; i < 8; i++) {
        int pl = pl_base + i;
        wAoff[i] = (uint32_t)(pl * 128 + ((c4 * 8) ^ ((pl & 7) << 4)));
    }

    // mma role: warp (mt, nt) owns D[mt*16..+15][nt*32..+31]
    const int mt = warp >> 1, nt = warp & 1;
    const int rowA = mt * 16 + (lane & 15);
    const uint32_t aBaseOff = (uint32_t)(rowA * 128);
    const uint32_t aXor = (uint32_t)((rowA & 7) << 4);
    const uint32_t aKh  = (uint32_t)((lane >> 4) << 4);
    // B ldmatrix lane address within a 512B x4 group: matrix lane>>3, row lane&7
    const uint32_t bLane = (uint32_t)(((lane >> 3) << 7) + ((lane & 7) << 4));

    float acc[4][4];
#pragma unroll
    for (int j = 0; j < 4; j++)
#pragma unroll
        for (int q = 0; q < 4; q++) acc[j][q] = 0.f;

#pragma unroll 1
    for (int phase = 0; phase < 3; phase++) {
        const int kt0 = phase * PH;
        const int ph_len = (phase < 2) ? PH : (K_ - 2 * PH);

        // ---- stage this phase's B images (block-wide) ----
        __syncthreads();
        {
            const uint4* src = reinterpret_cast<const uint4*>(g_wB + (size_t)kt0 * 16384);
            uint4* dst = reinterpret_cast<uint4*>(smem + SM_B);
            const int nvec = ph_len * 1024;
            for (int i = tid; i < nvec; i += THREADS)
                dst[i] = __ldg(&src[i]);
        }
        __syncthreads();

#pragma unroll 1
        for (int t = 0; t < ph_len; t++) {
            const int kt = kt0 + t;
            const int buf = kt & 1;
            char* AhP = smem + buf * 32768;
            char* AlP = AhP + 16384;
            const uint32_t AhB = sb + buf * 32768;
            const uint32_t AlB = AhB + 16384;
            const uint32_t Bt  = sb + SM_B + t * 16384;

            // ---- sampling: 8 points per warp ----
            const int kd = kt / 9, kh3 = (kt / 3) % 3, kw3 = kt % 3;
            const float* offk = offB + 3 * kt * P_;

#pragma unroll
            for (int i = 0; i < 8; i++) {
                const int p  = p0 + pl_base + i;
                const int od = p >> 10, oh = (p >> 5) & 31, ow = p & 31;

                float zd = (float)(od - 1 + kd)  + __ldg(offk + p);
                float zh = (float)(oh - 1 + kh3) + __ldg(offk + P_ + p);
                float zw = (float)(ow - 1 + kw3) + __ldg(offk + 2 * P_ + p);

                float fd = floorf(zd); int d0 = (int)fd; float rd = zd - fd;
                float fh = floorf(zh); int h0 = (int)fh; float rh = zh - fh;
                float fw = floorf(zw); int w0 = (int)fw; float rw = zw - fw;

                float wd = half ? (((unsigned)(d0 + 1) < (unsigned)D_) ? rd : 0.f)
                                : (((unsigned)d0 < (unsigned)D_) ? 1.f - rd : 0.f);
                float wh0 = ((unsigned)h0       < (unsigned)H_) ? 1.f - rh : 0.f;
                float wh1 = ((unsigned)(h0 + 1) < (unsigned)H_) ? rh       : 0.f;
                float ww0 = ((unsigned)w0       < (unsigned)W_) ? 1.f - rw : 0.f;
                float ww1 = ((unsigned)(w0 + 1) < (unsigned)W_) ? rw       : 0.f;

                // linear AND-wrap index: wrapped corners always carry weight 0
                const int s0 = (d0 + half) * 1024 + h0 * 32 + w0;
                const uint32_t i0 = ((uint32_t)s0        & 8191u) << 8;
                const uint32_t i1 = ((uint32_t)(s0 + 1)  & 8191u) << 8;
                const uint32_t i2 = ((uint32_t)(s0 + 32) & 8191u) << 8;
                const uint32_t i3 = ((uint32_t)(s0 + 33) & 8191u) << 8;
                const char* base2 = xb + (uint32_t)(c4 << 4);

                const float wdh0 = wd * wh0, wdh1 = wd * wh1;
                const float g0 = wdh0 * ww0, g1 = wdh0 * ww1;
                const float g2 = wdh1 * ww0, g3 = wdh1 * ww1;

                float4 v0 = __ldg(reinterpret_cast<const float4*>(base2 + i0));
                float4 v1 = __ldg(reinterpret_cast<const float4*>(base2 + i1));
                float4 v2 = __ldg(reinterpret_cast<const float4*>(base2 + i2));
                float4 v3 = __ldg(reinterpret_cast<const float4*>(base2 + i3));

                unsigned long long axy = 0ull, azw = 0ull;
                ffma2(axy, pk2(g0, g0), pk2(v0.x, v0.y));
                ffma2(azw, pk2(g0, g0), pk2(v0.z, v0.w));
                ffma2(axy, pk2(g1, g1), pk2(v1.x, v1.y));
                ffma2(azw, pk2(g1, g1), pk2(v1.z, v1.w));
                ffma2(axy, pk2(g2, g2), pk2(v2.x, v2.y));
                ffma2(azw, pk2(g2, g2), pk2(v2.z, v2.w));
                ffma2(axy, pk2(g3, g3), pk2(v3.x, v3.y));
                ffma2(azw, pk2(g3, g3), pk2(v3.z, v3.w));

                float2 vxy = upk(axy), vzw = upk(azw);
                float ax = vxy.x, ay = vxy.y, az = vzw.x, aw = vzw.y;
                ax += __shfl_down_sync(FULL, ax, 16);
                ay += __shfl_down_sync(FULL, ay, 16);
                az += __shfl_down_sync(FULL, az, 16);
                aw += __shfl_down_sync(FULL, aw, 16);

                if (half == 0) {
                    uint32_t h01 = bf16x2(ay, ax);       // hi=ch+1, lo=ch+0
                    uint32_t h23 = bf16x2(aw, az);
                    float hx = __uint_as_float(h01 << 16);
                    float hy = __uint_as_float(h01 & 0xffff0000u);
                    float hz = __uint_as_float(h23 << 16);
                    float hww = __uint_as_float(h23 & 0xffff0000u);
                    uint32_t l01 = bf16x2(ay - hy, ax - hx);
                    uint32_t l23 = bf16x2(aw - hww, az - hz);
                    *reinterpret_cast<uint2*>(AhP + wAoff[i]) = make_uint2(h01, h23);
                    *reinterpret_cast<uint2*>(AlP + wAoff[i]) = make_uint2(l01, l23);
                }
            }

            bar_pair(mt + 1);   // pair barrier (ids 1..8; bar0 = __syncthreads)

            // ---- A fragments: all 4 K-steps, hi+lo ----
            uint32_t ah[4][4], al[4][4];
#pragma unroll
            for (int ks = 0; ks < 4; ks++) {
                const uint32_t aoff = aBaseOff + (((uint32_t)(ks * 32) + aKh) ^ aXor);
                ldm_x4(ah[ks], AhB + aoff);
                ldm_x4(al[ks], AlB + aoff);
            }

            // ---- B fragments via ldmatrix + MMA ----
#pragma unroll
            for (int j = 0; j < 4; j++) {
                const uint32_t Bj = Bt + (uint32_t)((nt * 4 + j) * 2048) + bLane;
#pragma unroll
                for (int ks = 0; ks < 4; ks++) {
                    uint32_t bb[4];                    // hi-b0, hi-b1, lo-b0, lo-b1
                    ldm_x4(bb, Bj + (uint32_t)(ks * 512));
                    mma_bf16(acc[j], ah[ks], &bb[0]);  // Ah*Bh
                    mma_bf16(acc[j], al[ks], &bb[0]);  // Al*Bh
                    mma_bf16(acc[j], ah[ks], &bb[2]);  // Ah*Bl
                }
            }
            // A buf reuse at kt+2 ordered by bar_pair(kt+1)
        }
    }

    // ---- epilogue: D fragment scatter + bias ----
    const int m = lane >> 2;
    const int p = p0 + mt * 16 + m;
#pragma unroll
    for (int j = 0; j < 4; j++) {
        const int n = nt * 32 + j * 8 + 2 * (lane & 3);
        const float bv0 = __ldg(&bias[n]);
        const float bv1 = __ldg(&bias[n + 1]);
        float* o0 = out + ((size_t)(b * COUT_ + n)) * P_ + p;
        o0[0]      = acc[j][0] + bv0;
        o0[P_]     = acc[j][1] + bv1;
        o0[8]      = acc[j][2] + bv0;
        o0[P_ + 8] = acc[j][3] + bv1;
    }
}

extern "C" void kernel_launch(void* const* d_in, const int* in_sizes, int n_in,
                              void* d_out, int out_size) {
    const float* x      = (const float*)d_in[0];
    const float* offset = (const float*)d_in[1];
    const float* weight = (const float*)d_in[2];
    const float* bias   = (const float*)d_in[3];
    float* out = (float*)d_out;

    cudaFuncSetAttribute(deform_hmma_kernel,
                         cudaFuncAttributeMaxDynamicSharedMemorySize, SM_TOTAL);
    prep_kernel<<<256, 256>>>(x, weight);
    deform_hmma_kernel<<<NBLK, THREADS, SM_TOTAL>>>(offset, bias, out);
}